// round 1
// baseline (speedup 1.0000x reference)
#include <cuda_runtime.h>
#include <cstddef>

#define BATCH   256
#define IN_DIM  2048
#define OUT_DIM 2048
#define STEPS   40

// Scratch (static __device__ arrays; no allocation anywhere)
__device__ float d_wt[IN_DIM * OUT_DIM];            // transposed weight: wt[i][o]
__device__ int   d_list[BATCH * IN_DIM];            // input indices sorted by spike step, per batch
__device__ int   d_off [BATCH * (STEPS + 1)];       // per-batch step offsets into d_list

// ---------------------------------------------------------------------------
// Kernel 1: transpose weight [OUT][IN] -> wt [IN][OUT]
// ---------------------------------------------------------------------------
__global__ void transpose_kernel(const float* __restrict__ w)
{
    __shared__ float tile[32][33];
    int x = blockIdx.x * 32 + threadIdx.x;   // input index i
    int y = blockIdx.y * 32 + threadIdx.y;   // output index o
#pragma unroll
    for (int j = 0; j < 32; j += 8)
        tile[threadIdx.y + j][threadIdx.x] = w[(size_t)(y + j) * IN_DIM + x];
    __syncthreads();
    int xo = blockIdx.y * 32 + threadIdx.x;  // o
    int yo = blockIdx.x * 32 + threadIdx.y;  // i
#pragma unroll
    for (int j = 0; j < 32; j += 8)
        d_wt[(size_t)(yo + j) * OUT_DIM + xo] = tile[threadIdx.x][threadIdx.y + j];
}

// ---------------------------------------------------------------------------
// Kernel 2: per-batch counting sort of input indices by spike step.
// Spike times are exactly step*0.5 in fp32, so step = round(t*2) is exact.
// ---------------------------------------------------------------------------
__global__ void bucket_kernel(const float* __restrict__ inp)
{
    __shared__ int cnt[STEPS];
    __shared__ int cur[STEPS];
    const int b   = blockIdx.x;
    const int tid = threadIdx.x;

    if (tid < STEPS) cnt[tid] = 0;
    __syncthreads();

    for (int i = tid; i < IN_DIM; i += blockDim.x) {
        int s = (int)(inp[(size_t)b * IN_DIM + i] * 2.0f + 0.5f);
        atomicAdd(&cnt[s], 1);
    }
    __syncthreads();

    if (tid == 0) {
        int acc = 0;
        for (int k = 0; k < STEPS; k++) {
            int c = cnt[k];
            d_off[b * (STEPS + 1) + k] = acc;
            cur[k] = acc;
            acc += c;
        }
        d_off[b * (STEPS + 1) + STEPS] = acc;  // == IN_DIM
    }
    __syncthreads();

    for (int i = tid; i < IN_DIM; i += blockDim.x) {
        int s = (int)(inp[(size_t)b * IN_DIM + i] * 2.0f + 0.5f);
        int p = atomicAdd(&cur[s], 1);
        d_list[b * IN_DIM + p] = i;
    }
}

// ---------------------------------------------------------------------------
// Kernel 3: LIF dynamics with per-step gather of spiking inputs' weight rows.
// Block = (batch, 512-output tile). 256 threads, 2 outputs each via float2.
// Early exit when every output in the tile has spiked.
// ---------------------------------------------------------------------------
__global__ __launch_bounds__(256) void snn_kernel(float* __restrict__ out)
{
    const int bid = blockIdx.x;
    const int b   = bid >> 2;                       // batch
    const int oc  = (bid & 3) * 256 + threadIdx.x;  // float2 column index 0..1023

    const float2* __restrict__ wt2 = reinterpret_cast<const float2*>(d_wt) + oc;
    const int*    __restrict__ lst = d_list + b * IN_DIM;

    __shared__ int offs[STEPS + 1];
    if (threadIdx.x <= STEPS)
        offs[threadIdx.x] = d_off[b * (STEPS + 1) + threadIdx.x];
    __syncthreads();

    float Ix = 0.f, Iy = 0.f, Vx = 0.f, Vy = 0.f;
    float fx = 0.f, fy = 0.f;   // first-spike step (0 = not yet; step 0 can't spike)

    int j = 0;
    for (int k = 0; k < STEPS; k++) {
        // V <- V + (DT/TAU_M) * (I_prev - V)
        Vx += 0.025f * (Ix - Vx);
        Vy += 0.025f * (Iy - Vy);

        // gather weight rows of inputs spiking at this step
        const int e = offs[k + 1];
        float ax = 0.f, ay = 0.f;
        for (; j + 3 < e; j += 4) {
            int i0 = __ldg(lst + j);
            int i1 = __ldg(lst + j + 1);
            int i2 = __ldg(lst + j + 2);
            int i3 = __ldg(lst + j + 3);
            float2 w0 = __ldg(wt2 + ((size_t)i0 << 10));
            float2 w1 = __ldg(wt2 + ((size_t)i1 << 10));
            float2 w2 = __ldg(wt2 + ((size_t)i2 << 10));
            float2 w3 = __ldg(wt2 + ((size_t)i3 << 10));
            ax += (w0.x + w1.x) + (w2.x + w3.x);
            ay += (w0.y + w1.y) + (w2.y + w3.y);
        }
        for (; j < e; j++) {
            int i0 = __ldg(lst + j);
            float2 w0 = __ldg(wt2 + ((size_t)i0 << 10));
            ax += w0.x;
            ay += w0.y;
        }

        // I <- 0.9*I_prev + contribution
        Ix = 0.9f * Ix + ax;
        Iy = 0.9f * Iy + ay;

        // threshold, reset, record first spike
        if (Vx > 1.0f) { if (fx == 0.f) fx = (float)k; Vx = 0.f; }
        if (Vy > 1.0f) { if (fy == 0.f) fy = (float)k; Vy = 0.f; }

        // early exit: all outputs in this tile have spiked
        if (__syncthreads_and((fx != 0.f) && (fy != 0.f)))
            break;
    }

    float2 r;
    r.x = (fx == 0.f) ? 20.0f : fx;
    r.y = (fy == 0.f) ? 20.0f : fy;
    reinterpret_cast<float2*>(out)[(size_t)b * 1024 + oc] = r;
}

// ---------------------------------------------------------------------------
extern "C" void kernel_launch(void* const* d_in, const int* in_sizes, int n_in,
                              void* d_out, int out_size)
{
    const float* inp = (const float*)d_in[0];
    const float* w   = (const float*)d_in[1];
    // defensive: identify tensors by size (input=524288, weight=4194304)
    if (in_sizes[0] == IN_DIM * OUT_DIM) {
        const float* t = inp; inp = w; w = t;
    }

    transpose_kernel<<<dim3(IN_DIM / 32, OUT_DIM / 32), dim3(32, 8)>>>(w);
    bucket_kernel<<<BATCH, 256>>>(inp);
    snn_kernel<<<BATCH * 4, 256>>>((float*)d_out);
}